// round 10
// baseline (speedup 1.0000x reference)
#include <cuda_runtime.h>
#include <cuda_bf16.h>

// Problem constants (fixed by setup_inputs)
#define B_CHAIN 16384
#define S_SIDE  15
#define NATM    (1 + B_CHAIN + B_CHAIN * S_SIDE)   // 262145
#define NOUT    (NATM - 1)                         // 262144
#define NBLK    128
#define CHUNK   (B_CHAIN / NBLK)                   // 128 gen0 atoms / chains per block
#define K2_THR  512                                // 128 chains x 4 lanes
#define ATOMS_PER_BLK (CHUNK * (1 + S_SIDE))       // 2048
#define INV_THR 128
#define INV_BLKS (NOUT / INV_THR)                  // 2048

// Scratch (no cudaMalloc allowed)
__device__ float  g_btot[NBLK * 12];   // per-block gen0 chunk totals
__device__ int    g_inv[NOUT];         // inverse permutation of kin_id[1:]
__device__ float4 g_tmp4[NATM];        // coords by atom index (16B padded)

// C = A @ B for 3x4 rigid transforms, row-major [r00 r01 r02 tx | r1x | r2x]
__device__ __forceinline__ void compose(const float* __restrict__ A,
                                        const float* __restrict__ B,
                                        float* __restrict__ C) {
#pragma unroll
    for (int r = 0; r < 3; r++) {
        float a0 = A[r*4+0], a1 = A[r*4+1], a2 = A[r*4+2], a3 = A[r*4+3];
        C[r*4+0] = a0*B[0] + a1*B[4] + a2*B[8];
        C[r*4+1] = a0*B[1] + a1*B[5] + a2*B[9];
        C[r*4+2] = a0*B[2] + a1*B[6] + a2*B[10];
        C[r*4+3] = a0*B[3] + a1*B[7] + a2*B[11] + a3;
    }
}

__device__ __forceinline__ void mat_copy(float* __restrict__ d, const float* __restrict__ s) {
#pragma unroll
    for (int k = 0; k < 12; k++) d[k] = s[k];
}

__device__ __forceinline__ void mat_ident(float* __restrict__ d) {
    d[0]=1.f; d[1]=0.f; d[2]=0.f; d[3]=0.f;
    d[4]=0.f; d[5]=1.f; d[6]=0.f; d[7]=0.f;
    d[8]=0.f; d[9]=0.f; d[10]=1.f; d[11]=0.f;
}

// Bond transform: Rx(d0) Rz(d1) T(d2,0,0) Rx(d3), closed form.
// FAST (__sincosf) only on side chains (depth <= 15). Gen0 (16K deep) must use
// accurate sincosf: fast trig there measured rel_err 9e-4 (too close to 1e-3).
template <bool FAST>
__device__ __forceinline__ void bond_ht(float d0, float d1, float d2, float d3,
                                        float* __restrict__ M) {
    float sa, ca, sb, cb, sd, cd;
    if (FAST) {
        __sincosf(d0, &sa, &ca);
        __sincosf(d1, &sb, &cb);
        __sincosf(d3, &sd, &cd);
    } else {
        sincosf(d0, &sa, &ca);
        sincosf(d1, &sb, &cb);
        sincosf(d3, &sd, &cd);
    }
    M[0] = cb;     M[1] = -sb*cd;            M[2]  = sb*sd;             M[3]  = d2*cb;
    M[4] = ca*sb;  M[5] = ca*cb*cd - sa*sd;  M[6]  = -ca*cb*sd - sa*cd; M[7]  = ca*d2*sb;
    M[8] = sa*sb;  M[9] = sa*cb*cd + ca*sd;  M[10] = -sa*cb*sd + ca*cd; M[11] = sa*d2*sb;
}

// Atom 1 jump (d4=d5=0): T(d0,d1,d2) @ Rx(d3)
__device__ __forceinline__ void jump_ht(float d0, float d1, float d2, float d3,
                                        float* __restrict__ M) {
    float sd, cd; sincosf(d3, &sd, &cd);
    M[0] = 1.f; M[1] = 0.f; M[2] = 0.f;  M[3]  = d0;
    M[4] = 0.f; M[5] = cd;  M[6] = -sd;  M[7]  = d1;
    M[8] = 0.f; M[9] = sd;  M[10] = cd;  M[11] = d2;
}

__device__ __forceinline__ void shfl_up_mat(float* __restrict__ P,
                                            const float* __restrict__ M,
                                            int off, int width) {
#pragma unroll
    for (int k = 0; k < 12; k++)
        P[k] = __shfl_up_sync(0xffffffffu, M[k], off, width);
}

__device__ __forceinline__ void shfl_dn_mat(float* __restrict__ P,
                                            const float* __restrict__ M,
                                            int off) {
#pragma unroll
    for (int k = 0; k < 12; k++)
        P[k] = __shfl_down_sync(0xffffffffu, M[k], off);
}

// Local ht for gen0 index gi (atom gi+1), accurate trig
__device__ __forceinline__ void gen0_ht(const float* __restrict__ dofs,
                                        int gi, float* __restrict__ M) {
    const float4 d = __ldg((const float4*)(dofs + 4 * gi));
    if (gi == 0) jump_ht(d.x, d.y, d.z, d.w, M);
    else         bond_ht<false>(d.x, d.y, d.z, d.w, M);
}

// Warp inclusive scan (order-preserving, width 32)
__device__ __forceinline__ void warp_scan(float* __restrict__ M, int lane) {
#pragma unroll
    for (int off = 1; off < 32; off <<= 1) {
        float P[12], C[12];
        shfl_up_mat(P, M, off, 32);
        compose(P, M, C);
        if (lane >= off) mat_copy(M, C);
    }
}

// ---------------- K1: chunk totals (blocks 0..127) + inverse perm (rest) ----------------
__global__ void __launch_bounds__(INV_THR) k_pre(const float* __restrict__ dofs,
                                                 const int* __restrict__ kin_id) {
    if (blockIdx.x < NBLK) {
        __shared__ float s_w[4 * 12];
        const int tid  = threadIdx.x;
        const int lane = tid & 31;
        const int wid  = tid >> 5;
        const int gi   = blockIdx.x * CHUNK + tid;

        float M[12];
        gen0_ht(dofs, gi, M);

        // warp product reduction (order-preserving): lane0 = v0∘...∘v31
#pragma unroll
        for (int off = 1; off < 32; off <<= 1) {
            float P[12], C[12];
            shfl_dn_mat(P, M, off);
            compose(M, P, C);
            mat_copy(M, C);        // upper lanes garbage; lane0 correct
        }
        if (lane == 0) mat_copy(&s_w[wid * 12], M);
        __syncthreads();

        if (tid == 0) {
            float T[12], C[12];
            mat_copy(T, &s_w[0]);
#pragma unroll
            for (int i = 1; i < 4; i++) { compose(T, &s_w[i * 12], C); mat_copy(T, C); }
            mat_copy(&g_btot[blockIdx.x * 12], T);
        }
    } else {
        // build inverse permutation: g_inv[kin_id[a]] = a
        const int i = (blockIdx.x - NBLK) * INV_THR + threadIdx.x;  // 0..NOUT-1
        const int a = i + 1;
        g_inv[__ldg(&kin_id[a])] = a;
    }
}

// ---------------- K2: scan-redo + prefix + apply; coords -> g_tmp4 (coalesced) ----------------
__global__ void __launch_bounds__(K2_THR)
k_apply(const float* __restrict__ dofs) {
    __shared__ float  s_scan[CHUNK * 12];      // 6 KB
    __shared__ float  s_wA[4 * 12];
    __shared__ float  s_wB[4 * 12];
    __shared__ float  s_pref[12];
    __shared__ float4 s_out[ATOMS_PER_BLK];    // 32 KB staging

    const int b    = blockIdx.x;
    const int tid  = threadIdx.x;
    const int lane = tid & 31;

    float MA[12], MB[12];

    if (tid < CHUNK) {
        // Group A (warps 0-3): chunk inclusive scan (accurate trig)
        gen0_ht(dofs, b * CHUNK + tid, MA);
        warp_scan(MA, lane);
        if (lane == 31) mat_copy(&s_wA[(tid >> 5) * 12], MA);
    } else if (tid < 2 * CHUNK) {
        // Group B (warps 4-7): scan the 128 block totals
        const int t2 = tid - CHUNK;
        mat_copy(MB, &g_btot[t2 * 12]);
        warp_scan(MB, lane);
        if (lane == 31) mat_copy(&s_wB[(t2 >> 5) * 12], MB);
    }
    __syncthreads();

    if (tid < CHUNK) {
        const int wid = tid >> 5;
        float W[12]; mat_ident(W);
        for (int i = 0; i < wid; i++) {
            float C[12]; compose(W, &s_wA[i * 12], C); mat_copy(W, C);
        }
        float F[12]; compose(W, MA, F);
        mat_copy(&s_scan[tid * 12], F);
    } else if (tid < 2 * CHUNK) {
        const int t2  = tid - CHUNK;
        const int wid = t2 >> 5;
        float W[12]; mat_ident(W);
        for (int i = 0; i < wid; i++) {
            float C[12]; compose(W, &s_wB[i * 12], C); mat_copy(W, C);
        }
        float F[12]; compose(W, MB, F);      // inclusive over btot[0..t2]
        if (b == 0) {
            if (t2 == 0) { float I[12]; mat_ident(I); mat_copy(s_pref, I); }
        } else if (t2 == b - 1) {
            mat_copy(s_pref, F);
        }
    }
    __syncthreads();

    // Phase 3: 4 lanes per chain, 4 atoms serial per lane.
    // lane 0: parent + side atoms 0..2 ; lane j>0: side atoms 3+(j-1)*4 .. +3
    const int l = tid >> 2;
    const int j = tid & 3;
    const int c = b * CHUNK + l;
    const int sbase = B_CHAIN + c * S_SIDE;
    const int first = (j == 0) ? 0 : 3 + (j - 1) * 4;
    const int nA    = (j == 0) ? 3 : 4;

    float Lm[4][12];
#pragma unroll
    for (int i = 0; i < 4; i++) {
        if (i < nA) {
            const float4 d = __ldg((const float4*)(dofs + 4 * (sbase + first + i)));
            bond_ht<true>(d.x, d.y, d.z, d.w, Lm[i]);
        }
    }

    // smem slots: gen0 atom of chain l -> slot l; side atom s of chain l -> CHUNK + l*15 + s
    float S[12];
    if (j == 0) {
        compose(s_pref, &s_scan[l * 12], S);       // gen0 global
        s_out[l] = make_float4(S[3], S[7], S[11], 0.f);
#pragma unroll
        for (int i = 0; i < 3; i++) {
            float C[12]; compose(S, Lm[i], C); mat_copy(S, C);
            s_out[CHUNK + l * S_SIDE + i] = make_float4(S[3], S[7], S[11], 0.f);
        }
    } else {
        mat_copy(S, Lm[0]);
#pragma unroll
        for (int i = 1; i < 4; i++) {
            float C[12]; compose(S, Lm[i], C); mat_copy(S, C);
        }
    }

    // width-4 inclusive scan (2 steps)
#pragma unroll
    for (int off = 1; off < 4; off <<= 1) {
        float Q[12], C[12];
        shfl_up_mat(Q, S, off, 4);
        compose(Q, S, C);
        if (j >= off) mat_copy(S, C);
    }

    float X[12];
    shfl_up_mat(X, S, 1, 4);     // start for lane j = inclusive of lane j-1

    if (j > 0) {
        float cur[12];
        mat_copy(cur, X);
#pragma unroll
        for (int i = 0; i < 4; i++) {
            float C[12]; compose(cur, Lm[i], C); mat_copy(cur, C);
            s_out[CHUNK + l * S_SIDE + first + i] = make_float4(cur[3], cur[7], cur[11], 0.f);
        }
    }
    __syncthreads();

    // Coalesced copy to g_tmp4 (atom-indexed, two contiguous ranges)
    const int g0_base   = b * CHUNK + 1;               // atoms of gen0 chunk
    const int side_base = 1 + B_CHAIN + b * CHUNK * S_SIDE;
#pragma unroll
    for (int t = tid; t < CHUNK; t += K2_THR)
        g_tmp4[g0_base + t] = s_out[t];
    for (int t = tid; t < CHUNK * S_SIDE; t += K2_THR)
        g_tmp4[side_base + t] = s_out[CHUNK + t];
}

// ---------------- K3: out[o] = g_tmp4[g_inv[o]].xyz ----------------
__global__ void __launch_bounds__(256) k_gather(float* __restrict__ out) {
    const int o = blockIdx.x * 256 + threadIdx.x;      // 0..NOUT-1
    const int a = __ldg(&g_inv[o]);
    const float4 v = g_tmp4[a];
    out[3*o + 0] = v.x;
    out[3*o + 1] = v.y;
    out[3*o + 2] = v.z;
}

extern "C" void kernel_launch(void* const* d_in, const int* in_sizes, int n_in,
                              void* d_out, int out_size) {
    const float* dofs   = (const float*)d_in[0];   // (NATM-1)*4
    const int*   kin_id = (const int*)  d_in[8];   // NATM
    float*       out    = (float*)d_out;           // (NATM-1)*3

    k_pre<<<NBLK + INV_BLKS, INV_THR>>>(dofs, kin_id);
    k_apply<<<NBLK, K2_THR>>>(dofs);
    k_gather<<<NOUT / 256, 256>>>(out);
}